// round 1
// baseline (speedup 1.0000x reference)
#include <cuda_runtime.h>
#include <math.h>

// Problem constants (fixed by the dataset)
#define NROWS 4096          // B*S
#define HDIM  2048
#define VDIM  32000
#define BATCH 4
#define SEQ   1024
#define BETA_C 0.1f

// GEMM tiling
#define BM 128
#define BN 64
#define BK 32
#define NCHUNK (VDIM / BN)        // 500
#define ROW_TILES (NROWS / BM)    // 32

// ---------------- scratch (allocation-free: __device__ globals) ----------------
__device__ float g_m1[NROWS * NCHUNK];
__device__ float g_m2[NROWS * NCHUNK];
__device__ int   g_i1[NROWS * NCHUNK];
__device__ int   g_i2[NROWS * NCHUNK];
__device__ float g_s [NROWS * NCHUNK];
__device__ float g_rm[NROWS * NCHUNK];
__device__ float g_rs[NROWS * NCHUNK];

__device__ float g_lse [NROWS];
__device__ float g_rlse[NROWS];
__device__ int   g_c1  [NROWS];
__device__ int   g_c2  [NROWS];
__device__ float g_tl  [NROWS];

// ---------------- helpers ----------------
__device__ __forceinline__ bool better(float va, int ia, float vb, int ib) {
    // strict ordering with jnp.argmax tie-break (first/lowest index wins)
    return (va > vb) || (va == vb && ia < ib);
}

__device__ __forceinline__ void top2_insert(float v, int i,
                                            float& m1, int& i1, float& m2, int& i2) {
    if (better(v, i, m1, i1)) { m2 = m1; i2 = i1; m1 = v; i1 = i; }
    else if (better(v, i, m2, i2)) { m2 = v; i2 = i; }
}

// online logsumexp partial merge: (mm, ss) <- merge (cm, cs)
__device__ __forceinline__ void lse_merge(float& mm, float& ss, float cm, float cs) {
    if (cm > mm) { ss = ss * __expf(mm - cm) + cs; mm = cm; }
    else if (cm > -INFINITY) { ss += cs * __expf(cm - mm); }
}

// ---------------- K1/K2: fused GEMM + per-chunk row reduction ----------------
// C[m][n] = sum_k A[m][k] * W[n][k] + bias[n]; reduce each 64-col chunk per row.
// POLICY: track top-2 (value,index) + sumexp.  !POLICY: max + sumexp only.
template<bool POLICY>
__global__ __launch_bounds__(256)
void gemm_reduce_kernel(const float* __restrict__ A,
                        const float* __restrict__ W,
                        const float* __restrict__ bias)
{
    __shared__ __align__(16) float As[BK][BM + 4];
    __shared__ __align__(16) float Bs[BK][BN + 4];

    const int bn0 = blockIdx.x * BN;
    const int rm0 = blockIdx.y * BM;
    const int tid = threadIdx.x;
    const int tx = tid & 15;          // 0..15  -> 4 cols each
    const int ty = tid >> 4;          // 0..15  -> 8 rows each

    float acc[8][4];
#pragma unroll
    for (int i = 0; i < 8; i++)
#pragma unroll
        for (int j = 0; j < 4; j++) acc[i][j] = 0.0f;

    for (int k0 = 0; k0 < HDIM; k0 += BK) {
        // load A tile (128x32) transposed into As[k][m]
#pragma unroll
        for (int i = 0; i < 4; i++) {
            int idx = (tid + i * 256) * 4;          // 0..4092
            int r = idx >> 5;
            int c = idx & 31;
            float4 v = *(const float4*)(A + (size_t)(rm0 + r) * HDIM + k0 + c);
            As[c + 0][r] = v.x; As[c + 1][r] = v.y;
            As[c + 2][r] = v.z; As[c + 3][r] = v.w;
        }
        // load W tile (64x32) transposed into Bs[k][n]
#pragma unroll
        for (int i = 0; i < 2; i++) {
            int idx = (tid + i * 256) * 4;          // 0..2044
            int n = idx >> 5;
            int c = idx & 31;
            float4 v = *(const float4*)(W + (size_t)(bn0 + n) * HDIM + k0 + c);
            Bs[c + 0][n] = v.x; Bs[c + 1][n] = v.y;
            Bs[c + 2][n] = v.z; Bs[c + 3][n] = v.w;
        }
        __syncthreads();

#pragma unroll 8
        for (int k = 0; k < BK; k++) {
            float4 a0 = *(const float4*)&As[k][ty * 8];
            float4 a1 = *(const float4*)&As[k][ty * 8 + 4];
            float4 bv = *(const float4*)&Bs[k][tx * 4];
            float a[8] = {a0.x, a0.y, a0.z, a0.w, a1.x, a1.y, a1.z, a1.w};
            float b[4] = {bv.x, bv.y, bv.z, bv.w};
#pragma unroll
            for (int i = 0; i < 8; i++)
#pragma unroll
                for (int j = 0; j < 4; j++)
                    acc[i][j] = fmaf(a[i], b[j], acc[i][j]);
        }
        __syncthreads();
    }

    // epilogue: add bias, reduce each row across the 16 tx lanes (within half-warp)
    float4 bv = *(const float4*)(bias + bn0 + tx * 4);
    const float bb[4] = {bv.x, bv.y, bv.z, bv.w};
    const int c0 = bn0 + tx * 4;

#pragma unroll
    for (int i = 0; i < 8; i++) {
        float v[4];
#pragma unroll
        for (int j = 0; j < 4; j++) v[j] = acc[i][j] + bb[j];

        const int row = rm0 + ty * 8 + i;
        const int pidx = row * NCHUNK + blockIdx.x;

        if (POLICY) {
            float m1 = v[0]; int i1 = c0;
            float m2 = -INFINITY; int i2 = 0x7fffffff;
            top2_insert(v[1], c0 + 1, m1, i1, m2, i2);
            top2_insert(v[2], c0 + 2, m1, i1, m2, i2);
            top2_insert(v[3], c0 + 3, m1, i1, m2, i2);
#pragma unroll
            for (int off = 8; off >= 1; off >>= 1) {
                float om1 = __shfl_xor_sync(0xffffffffu, m1, off);
                int   oi1 = __shfl_xor_sync(0xffffffffu, i1, off);
                float om2 = __shfl_xor_sync(0xffffffffu, m2, off);
                int   oi2 = __shfl_xor_sync(0xffffffffu, i2, off);
                top2_insert(om1, oi1, m1, i1, m2, i2);
                top2_insert(om2, oi2, m1, i1, m2, i2);
            }
            float s = __expf(v[0] - m1) + __expf(v[1] - m1) +
                      __expf(v[2] - m1) + __expf(v[3] - m1);
#pragma unroll
            for (int off = 8; off >= 1; off >>= 1)
                s += __shfl_xor_sync(0xffffffffu, s, off);
            if (tx == 0) {
                g_m1[pidx] = m1; g_i1[pidx] = i1;
                g_m2[pidx] = m2; g_i2[pidx] = i2;
                g_s[pidx] = s;
            }
        } else {
            float m = fmaxf(fmaxf(v[0], v[1]), fmaxf(v[2], v[3]));
#pragma unroll
            for (int off = 8; off >= 1; off >>= 1)
                m = fmaxf(m, __shfl_xor_sync(0xffffffffu, m, off));
            float s = __expf(v[0] - m) + __expf(v[1] - m) +
                      __expf(v[2] - m) + __expf(v[3] - m);
#pragma unroll
            for (int off = 8; off >= 1; off >>= 1)
                s += __shfl_xor_sync(0xffffffffu, s, off);
            if (tx == 0) {
                g_rm[pidx] = m; g_rs[pidx] = s;
            }
        }
    }
}

// ---------------- K3: merge per-chunk partials -> per-row results ----------------
template<bool POLICY>
__global__ __launch_bounds__(256)
void merge_kernel()
{
    const int warp = blockIdx.x * (blockDim.x >> 5) + (threadIdx.x >> 5);
    const int lane = threadIdx.x & 31;
    if (warp >= NROWS) return;
    const int row = warp;

    float m1 = -INFINITY; int i1 = 0x7fffffff;
    float m2 = -INFINITY; int i2 = 0x7fffffff;
    float mm = -INFINITY, ss = 0.0f;

    for (int c = lane; c < NCHUNK; c += 32) {
        const int idx = row * NCHUNK + c;
        if (POLICY) {
            float cm1 = g_m1[idx]; int ci1 = g_i1[idx];
            float cm2 = g_m2[idx]; int ci2 = g_i2[idx];
            float cs  = g_s[idx];
            top2_insert(cm1, ci1, m1, i1, m2, i2);
            top2_insert(cm2, ci2, m1, i1, m2, i2);
            lse_merge(mm, ss, cm1, cs);
        } else {
            lse_merge(mm, ss, g_rm[idx], g_rs[idx]);
        }
    }
#pragma unroll
    for (int off = 16; off >= 1; off >>= 1) {
        if (POLICY) {
            float om1 = __shfl_xor_sync(0xffffffffu, m1, off);
            int   oi1 = __shfl_xor_sync(0xffffffffu, i1, off);
            float om2 = __shfl_xor_sync(0xffffffffu, m2, off);
            int   oi2 = __shfl_xor_sync(0xffffffffu, i2, off);
            top2_insert(om1, oi1, m1, i1, m2, i2);
            top2_insert(om2, oi2, m1, i1, m2, i2);
        }
        float omm = __shfl_xor_sync(0xffffffffu, mm, off);
        float oss = __shfl_xor_sync(0xffffffffu, ss, off);
        lse_merge(mm, ss, omm, oss);
    }
    if (lane == 0) {
        if (POLICY) {
            g_lse[row] = mm + logf(ss);
            g_c1[row] = i1; g_c2[row] = i2;
        } else {
            g_rlse[row] = mm + logf(ss);
        }
    }
}

// ---------------- K4: exact fp32 re-dot of top-2 candidates + per-token loss ----------------
__global__ __launch_bounds__(128)
void pick_loss_kernel(const float* __restrict__ x,   const float* __restrict__ w,
                      const float* __restrict__ bias,
                      const float* __restrict__ rx,  const float* __restrict__ rw,
                      const float* __restrict__ rbias,
                      const float* __restrict__ adv, const int* __restrict__ amask)
{
    const int row = blockIdx.x;
    const int tid = threadIdx.x;
    const int lane = tid & 31;
    const int wid = tid >> 5;

    const int i1 = g_c1[row];
    const int i2 = g_c2[row];

    const float4* xa = (const float4*)(x + (size_t)row * HDIM);
    const float4* w1 = (const float4*)(w + (size_t)i1 * HDIM);
    const float4* w2 = (const float4*)(w + (size_t)i2 * HDIM);

    float a1 = 0.0f, a2 = 0.0f;
    for (int k = tid; k < HDIM / 4; k += 128) {
        float4 xv = xa[k];
        float4 v1 = w1[k];
        float4 v2 = w2[k];
        a1 += xv.x * v1.x + xv.y * v1.y + xv.z * v1.z + xv.w * v1.w;
        a2 += xv.x * v2.x + xv.y * v2.y + xv.z * v2.z + xv.w * v2.w;
    }
#pragma unroll
    for (int off = 16; off >= 1; off >>= 1) {
        a1 += __shfl_down_sync(0xffffffffu, a1, off);
        a2 += __shfl_down_sync(0xffffffffu, a2, off);
    }
    __shared__ float r1[4], r2[4];
    __shared__ int s_chosen;
    __shared__ float s_clogit;
    if (lane == 0) { r1[wid] = a1; r2[wid] = a2; }
    __syncthreads();
    if (tid == 0) {
        float t1 = r1[0] + r1[1] + r1[2] + r1[3] + bias[i1];
        float t2 = r2[0] + r2[1] + r2[2] + r2[3] + bias[i2];
        if (better(t2, i2, t1, i1)) { s_chosen = i2; s_clogit = t2; }
        else                        { s_chosen = i1; s_clogit = t1; }
    }
    __syncthreads();

    const int ch = s_chosen;
    const float4* rxa = (const float4*)(rx + (size_t)row * HDIM);
    const float4* wr  = (const float4*)(rw + (size_t)ch * HDIM);
    float ar = 0.0f;
    for (int k = tid; k < HDIM / 4; k += 128) {
        float4 xv = rxa[k];
        float4 vv = wr[k];
        ar += xv.x * vv.x + xv.y * vv.y + xv.z * vv.z + xv.w * vv.w;
    }
#pragma unroll
    for (int off = 16; off >= 1; off >>= 1)
        ar += __shfl_down_sync(0xffffffffu, ar, off);
    if (lane == 0) r1[wid] = ar;
    __syncthreads();
    if (tid == 0) {
        float ref_logit = r1[0] + r1[1] + r1[2] + r1[3] + rbias[ch];
        float chosen_lp = s_clogit - g_lse[row];
        float ref_lp = ref_logit - g_rlse[row];

        float advb = adv[row >> 10];   // row / SEQ -> batch index
        // coef_1 = exp(chosen_lp - stop_grad(chosen_lp)) = 1; coef_2 = clip(1) = 1
        float ptl = -fminf(advb, advb);           // = -advb
        float d = ref_lp - chosen_lp;
        ptl += BETA_C * (expf(d) - d - 1.0f);
        g_tl[row] = ptl * (float)amask[row];
    }
}

// ---------------- K5: final masked mean ----------------
__global__ __launch_bounds__(1024)
void finalize_kernel(const int* __restrict__ amask, float* __restrict__ out, int out_size)
{
    const int tid = threadIdx.x;
    const int lane = tid & 31;
    const int wid = tid >> 5;
    float ls = 0.0f, ms = 0.0f;
    for (int i = tid; i < NROWS; i += 1024) {
        ls += g_tl[i];
        ms += (float)amask[i];
    }
#pragma unroll
    for (int off = 16; off >= 1; off >>= 1) {
        ls += __shfl_down_sync(0xffffffffu, ls, off);
        ms += __shfl_down_sync(0xffffffffu, ms, off);
    }
    __shared__ float sl[32], sm[32];
    __shared__ float s_loss;
    if (lane == 0) { sl[wid] = ls; sm[wid] = ms; }
    __syncthreads();
    if (tid == 0) {
        float tl = 0.0f, tm = 0.0f;
        for (int i = 0; i < 32; i++) { tl += sl[i]; tm += sm[i]; }
        s_loss = tl / fmaxf(tm, 1.0f);
    }
    __syncthreads();
    for (int i = tid; i < out_size; i += 1024) out[i] = s_loss;
}

// ---------------- entry point ----------------
extern "C" void kernel_launch(void* const* d_in, const int* in_sizes, int n_in,
                              void* d_out, int out_size)
{
    const float* x     = (const float*)d_in[0];
    const float* w     = (const float*)d_in[1];
    const float* bias  = (const float*)d_in[2];
    const float* rx    = (const float*)d_in[3];
    const float* rw    = (const float*)d_in[4];
    const float* rb    = (const float*)d_in[5];
    const float* adv   = (const float*)d_in[6];
    const int*   amask = (const int*)d_in[7];

    dim3 grid(NCHUNK, ROW_TILES);
    gemm_reduce_kernel<true><<<grid, 256>>>(x, w, bias);
    gemm_reduce_kernel<false><<<grid, 256>>>(rx, rw, rb);

    merge_kernel<true><<<NROWS / 8, 256>>>();
    merge_kernel<false><<<NROWS / 8, 256>>>();

    pick_loss_kernel<<<NROWS, 128>>>(x, w, bias, rx, rw, rb, adv, amask);
    finalize_kernel<<<1, 1024>>>(amask, (float*)d_out, out_size);
}

// round 3
// speedup vs baseline: 7.1615x; 7.1615x over previous
#include <cuda_runtime.h>
#include <cuda_bf16.h>
#include <math.h>
#include <stdint.h>

// Problem constants
#define NROWS 4096
#define HDIM  2048
#define VDIM  32000
#define BETA_C 0.1f

// GEMM tiling
#define BM 128
#define BN 128
#define BK 32
#define STAGES 4
#define KITER (HDIM / BK)     // 64
#define NCHUNK (VDIM / BN)    // 250
#define MTILES (NROWS / BM)   // 32

// smem layout (dynamic, 128B-aligned base)
#define STAGE_BYTES 16384     // A 8KB + B 8KB
#define BIAS_OFF (STAGES * STAGE_BYTES)          // 65536
#define RED_M1   (BIAS_OFF + 512)
#define RED_I1   (RED_M1 + 2048)
#define RED_M2   (RED_I1 + 2048)
#define RED_I2   (RED_M2 + 2048)
#define RED_S    (RED_I2 + 2048)
#define SMEM_TOTAL (RED_S + 2048 + 128)          // + align slack

// ---------------- scratch (__device__ globals; no allocation) ----------------
__device__ __nv_bfloat16 g_xb [NROWS * HDIM];
__device__ __nv_bfloat16 g_wb [(size_t)VDIM * HDIM];
__device__ __nv_bfloat16 g_rxb[NROWS * HDIM];
__device__ __nv_bfloat16 g_rwb[(size_t)VDIM * HDIM];

__device__ float g_m1[NROWS * NCHUNK];
__device__ float g_m2[NROWS * NCHUNK];
__device__ int   g_i1[NROWS * NCHUNK];
__device__ int   g_i2[NROWS * NCHUNK];
__device__ float g_s [NROWS * NCHUNK];
__device__ float g_rm[NROWS * NCHUNK];
__device__ float g_rs[NROWS * NCHUNK];

__device__ float g_lse [NROWS];
__device__ float g_rlse[NROWS];
__device__ int   g_c1  [NROWS];
__device__ int   g_c2  [NROWS];
__device__ float g_tl  [NROWS];

// ---------------- low-level helpers ----------------
__device__ __forceinline__ uint32_t smem_to_u32(const void* p) {
    uint32_t a;
    asm("{ .reg .u64 t; cvta.to.shared.u64 t, %1; cvt.u32.u64 %0, t; }" : "=r"(a) : "l"(p));
    return a;
}
__device__ __forceinline__ void cpa16(uint32_t saddr, const void* g) {
    asm volatile("cp.async.cg.shared.global [%0], [%1], 16;" :: "r"(saddr), "l"(g));
}
#define CP_COMMIT() asm volatile("cp.async.commit_group;" ::: "memory")

__device__ __forceinline__ void ldm_x4(uint32_t* r, uint32_t addr) {
    asm volatile("ldmatrix.sync.aligned.m8n8.x4.shared.b16 {%0,%1,%2,%3}, [%4];"
        : "=r"(r[0]), "=r"(r[1]), "=r"(r[2]), "=r"(r[3]) : "r"(addr));
}
__device__ __forceinline__ void mma_bf16(float* c, const uint32_t* a, const uint32_t* b) {
    asm volatile("mma.sync.aligned.m16n8k16.row.col.f32.bf16.bf16.f32 "
        "{%0,%1,%2,%3}, {%4,%5,%6,%7}, {%8,%9}, {%0,%1,%2,%3};"
        : "+f"(c[0]), "+f"(c[1]), "+f"(c[2]), "+f"(c[3])
        : "r"(a[0]), "r"(a[1]), "r"(a[2]), "r"(a[3]), "r"(b[0]), "r"(b[1]));
}

// tile: 128 rows x 32 bf16 cols (64B/row), packed 2 rows per 128B line, SW128-swizzled.
// row 0..127, c = 16B chunk 0..3
__device__ __forceinline__ uint32_t tile_off(int row, int c) {
    uint32_t raw = ((uint32_t)(row >> 1) << 7) | ((uint32_t)(row & 1) << 6) | ((uint32_t)c << 4);
    return raw ^ ((raw >> 3) & 0x70);
}

// ---------------- math helpers ----------------
__device__ __forceinline__ bool better(float va, int ia, float vb, int ib) {
    return (va > vb) || (va == vb && ia < ib);
}
__device__ __forceinline__ void top2_insert(float v, int i,
                                            float& m1, int& i1, float& m2, int& i2) {
    if (better(v, i, m1, i1)) { m2 = m1; i2 = i1; m1 = v; i1 = i; }
    else if (better(v, i, m2, i2)) { m2 = v; i2 = i; }
}
__device__ __forceinline__ void lse_merge(float& mm, float& ss, float cm, float cs) {
    if (cm > mm) { ss = ss * __expf(mm - cm) + cs; mm = cm; }
    else if (cm > -INFINITY) { ss += cs * __expf(cm - mm); }
}

// ---------------- K0: fp32 -> bf16 ----------------
__global__ __launch_bounds__(256)
void cvt_kernel(const float* __restrict__ src, __nv_bfloat16* __restrict__ dst, int n4)
{
    int i = blockIdx.x * blockDim.x + threadIdx.x;
    if (i < n4) {
        float4 v = ((const float4*)src)[i];
        __nv_bfloat162* d2 = (__nv_bfloat162*)dst;
        d2[i * 2 + 0] = __float22bfloat162_rn(make_float2(v.x, v.y));
        d2[i * 2 + 1] = __float22bfloat162_rn(make_float2(v.z, v.w));
    }
}

// ---------------- K1/K2: bf16 HMMA GEMM + fused row reduction ----------------
__device__ __forceinline__ void load_stage(uint32_t sbase, int st,
    const __nv_bfloat16* __restrict__ A, const __nv_bfloat16* __restrict__ W,
    int m0, int n0, int k0, int tid)
{
    uint32_t abase = sbase + st * STAGE_BYTES;
    uint32_t bbase = abase + 8192;
#pragma unroll
    for (int i = 0; i < 2; i++) {
        int idx = tid + i * 256;
        int row = idx >> 2, c = idx & 3;
        cpa16(abase + tile_off(row, c), A + (size_t)(m0 + row) * HDIM + k0 + c * 8);
    }
#pragma unroll
    for (int i = 0; i < 2; i++) {
        int idx = tid + i * 256;
        int row = idx >> 2, c = idx & 3;
        cpa16(bbase + tile_off(row, c), W + (size_t)(n0 + row) * HDIM + k0 + c * 8);
    }
    CP_COMMIT();
}

template<bool POLICY>
__global__ __launch_bounds__(256, 2)
void gemm_hmma(const __nv_bfloat16* __restrict__ A, const __nv_bfloat16* __restrict__ W,
               const float* __restrict__ bias)
{
    extern __shared__ __align__(16) char smem_raw[];
    const uint32_t raw32 = smem_to_u32(smem_raw);
    const uint32_t sbase = (raw32 + 127) & ~127u;
    char* cbase = smem_raw + (sbase - raw32);

    const int tid  = threadIdx.x;
    const int wid  = tid >> 5;
    const int lane = tid & 31;
    const int m0 = blockIdx.x * BM;
    const int n0 = blockIdx.y * BN;

    const int wm = (wid >> 2) * 64;     // warp m offset in tile
    const int wn = (wid & 3) * 32;      // warp n offset in tile

    float* s_bias = (float*)(cbase + BIAS_OFF);
    for (int i = tid; i < BN; i += 256) s_bias[i] = bias[n0 + i];

    float acc[4][4][4];
#pragma unroll
    for (int a = 0; a < 4; a++)
#pragma unroll
        for (int b = 0; b < 4; b++)
#pragma unroll
            for (int c = 0; c < 4; c++) acc[a][b][c] = 0.0f;

    // prologue: stages 0..2
#pragma unroll
    for (int s = 0; s < STAGES - 1; s++)
        load_stage(sbase, s, A, W, m0, n0, s * BK, tid);

    const int blk = lane >> 3, rowin = lane & 7;

#pragma unroll 1
    for (int it = 0; it < KITER; it++) {
        const int rs = it & (STAGES - 1);
        asm volatile("cp.async.wait_group %0;" :: "n"(STAGES - 2) : "memory");
        __syncthreads();

        if (it + STAGES - 1 < KITER)
            load_stage(sbase, (it + STAGES - 1) & (STAGES - 1), A, W, m0, n0,
                       (it + STAGES - 1) * BK, tid);
        else
            CP_COMMIT();   // keep group count in lockstep for wait_group

        const uint32_t abase = sbase + rs * STAGE_BYTES;
        const uint32_t bbase = abase + 8192;

#pragma unroll
        for (int kk = 0; kk < 2; kk++) {
            uint32_t af[4][4];
#pragma unroll
            for (int mt = 0; mt < 4; mt++) {
                int r = wm + mt * 16 + (blk & 1) * 8 + rowin;
                int c = kk * 2 + (blk >> 1);
                ldm_x4(af[mt], abase + tile_off(r, c));
            }
            uint32_t bf[4][2];
#pragma unroll
            for (int bt = 0; bt < 2; bt++) {
                int r = wn + bt * 16 + (blk & 1) * 8 + rowin;
                int c = kk * 2 + (blk >> 1);
                uint32_t t[4];
                ldm_x4(t, bbase + tile_off(r, c));
                bf[bt * 2 + 0][0] = t[0]; bf[bt * 2 + 0][1] = t[2];
                bf[bt * 2 + 1][0] = t[1]; bf[bt * 2 + 1][1] = t[3];
            }
#pragma unroll
            for (int mt = 0; mt < 4; mt++)
#pragma unroll
                for (int nt = 0; nt < 4; nt++)
                    mma_bf16(acc[mt][nt], af[mt], bf[nt]);
        }
    }

    // ---------------- fused epilogue ----------------
    float* sm1 = (float*)(cbase + RED_M1);
    int*   si1 = (int*)  (cbase + RED_I1);
    float* sm2 = (float*)(cbase + RED_M2);
    int*   si2 = (int*)  (cbase + RED_I2);
    float* ssm = (float*)(cbase + RED_S);

    const int lgrp = lane >> 2;
    const int lsub = lane & 3;

#pragma unroll
    for (int mt = 0; mt < 4; mt++) {
#pragma unroll
        for (int half = 0; half < 2; half++) {
            const int rloc = wm + mt * 16 + half * 8 + lgrp;
            float v[8];
            int   gi[8];
#pragma unroll
            for (int nt = 0; nt < 4; nt++)
#pragma unroll
                for (int j = 0; j < 2; j++) {
                    int ncol = wn + nt * 8 + lsub * 2 + j;
                    v[nt * 2 + j]  = acc[mt][nt][half * 2 + j] + s_bias[ncol];
                    gi[nt * 2 + j] = n0 + ncol;
                }
            float m1 = v[0]; int i1 = gi[0];
            float m2 = -INFINITY; int i2 = 0x7fffffff;
#pragma unroll
            for (int q = 1; q < 8; q++) top2_insert(v[q], gi[q], m1, i1, m2, i2);
            float s = 0.0f;
#pragma unroll
            for (int q = 0; q < 8; q++) s += __expf(v[q] - m1);

            // merge across the 4 lanes that share this row
#pragma unroll
            for (int off = 1; off <= 2; off <<= 1) {
                float om1 = __shfl_xor_sync(0xffffffffu, m1, off);
                int   oi1 = __shfl_xor_sync(0xffffffffu, i1, off);
                float os  = __shfl_xor_sync(0xffffffffu, s,  off);
                if (POLICY) {
                    float om2 = __shfl_xor_sync(0xffffffffu, m2, off);
                    int   oi2 = __shfl_xor_sync(0xffffffffu, i2, off);
                    // merge lse partial first (uses om1 as other's max)
                    lse_merge(m1 == fmaxf(m1, om1) ? m1 : m1, s, om1, os); // placeholder, replaced below
                    (void)om2; (void)oi2;
                }
                (void)om1; (void)oi1; (void)os;
            }
            // NOTE: careful merge done explicitly (the loop above is rewritten here):
            // redo cleanly:
            ;
            // --- clean cross-lane merge ---
            // (recompute from scratch to avoid the placeholder above)
            {
                // reset: recompute local from v/gi
                m1 = v[0]; i1 = gi[0]; m2 = -INFINITY; i2 = 0x7fffffff;
#pragma unroll
                for (int q = 1; q < 8; q++) top2_insert(v[q], gi[q], m1, i1, m2, i2);
                s = 0.0f;
#pragma unroll
                for (int q = 0; q < 8; q++) s += __expf(v[q] - m1);
                float mm = m1, ss = s;
#pragma unroll
                for (int off = 1; off <= 2; off <<= 1) {
                    float omm = __shfl_xor_sync(0xffffffffu, mm, off);
                    float oss = __shfl_xor_sync(0xffffffffu, ss, off);
                    float om1 = __shfl_xor_sync(0xffffffffu, m1, off);
                    int   oi1 = __shfl_xor_sync(0xffffffffu, i1, off);
                    float om2 = __shfl_xor_sync(0xffffffffu, m2, off);
                    int   oi2 = __shfl_xor_sync(0xffffffffu, i2, off);
                    lse_merge(mm, ss, omm, oss);
                    if (POLICY) {
                        top2_insert(om1, oi1, m1, i1, m2, i2);
                        top2_insert(om2, oi2, m1, i1, m2, i2);
                    } else {
                        m1 = fmaxf(m1, om1);
                    }
                }
                if (lsub == 0) {
                    const int slot = rloc * 4 + (wid & 3);
                    sm1[slot] = POLICY ? m1 : mm;
                    ssm[slot] = ss;
                    // store mm too for lse when POLICY (mm == m1 numerically; use mm)
                    if (POLICY) {
                        si1[slot] = i1;
                        sm2[slot] = m2;
                        si2[slot] = i2;
                        // lse partial max must be mm (==m1); they're equal since m1 is true max
                        sm1[slot] = m1;
                    }
                }
            }
        }
    }
    __syncthreads();

    if (tid < BM) {
        float m1 = -INFINITY; int i1 = 0x7fffffff;
        float m2 = -INFINITY; int i2 = 0x7fffffff;
        float mm = -INFINITY, ss = 0.0f;
#pragma unroll
        for (int w = 0; w < 4; w++) {
            const int slot = tid * 4 + w;
            float cm = sm1[slot];
            float cs = ssm[slot];
            lse_merge(mm, ss, cm, cs);
            if (POLICY) {
                top2_insert(cm, si1[slot], m1, i1, m2, i2);
                top2_insert(sm2[slot], si2[slot], m1, i1, m2, i2);
            }
        }
        const int grow = m0 + tid;
        const int pidx = grow * NCHUNK + blockIdx.y;
        if (POLICY) {
            g_m1[pidx] = m1; g_i1[pidx] = i1;
            g_m2[pidx] = m2; g_i2[pidx] = i2;
            g_s[pidx] = ss * __expf(mm - m1);   // renormalize sum to max m1 (mm==m1)
        } else {
            g_rm[pidx] = mm; g_rs[pidx] = ss;
        }
    }
}

// ---------------- K3: merge per-chunk partials -> per-row ----------------
template<bool POLICY>
__global__ __launch_bounds__(256)
void merge_kernel()
{
    const int warp = blockIdx.x * (blockDim.x >> 5) + (threadIdx.x >> 5);
    const int lane = threadIdx.x & 31;
    if (warp >= NROWS) return;
    const int row = warp;

    float m1 = -INFINITY; int i1 = 0x7fffffff;
    float m2 = -INFINITY; int i2 = 0x7fffffff;
    float mm = -INFINITY, ss = 0.0f;

    for (int c = lane; c < NCHUNK; c += 32) {
        const int idx = row * NCHUNK + c;
        if (POLICY) {
            float cm1 = g_m1[idx]; int ci1 = g_i1[idx];
            float cm2 = g_m2[idx]; int ci2 = g_i2[idx];
            float cs  = g_s[idx];
            top2_insert(cm1, ci1, m1, i1, m2, i2);
            top2_insert(cm2, ci2, m1, i1, m2, i2);
            lse_merge(mm, ss, cm1, cs);
        } else {
            lse_merge(mm, ss, g_rm[idx], g_rs[idx]);
        }
    }
#pragma unroll
    for (int off = 16; off >= 1; off >>= 1) {
        if (POLICY) {
            float om1 = __shfl_xor_sync(0xffffffffu, m1, off);
            int   oi1 = __shfl_xor_sync(0xffffffffu, i1, off);
            float om2 = __shfl_xor_sync(0xffffffffu, m2, off);
            int   oi2 = __shfl_xor_sync(0xffffffffu, i2, off);
            top2_insert(om1, oi1, m1, i1, m2, i2);
            top2_insert(om2, oi2, m1, i1, m2, i2);
        }
        float omm = __shfl_xor_sync(0xffffffffu, mm, off);
        float oss = __shfl_xor_sync(0xffffffffu, ss, off);
        lse_merge(mm, ss, omm, oss);
    }
    if (lane == 0) {
        if (POLICY) {
            g_lse[row] = mm + logf(ss);
            g_c1[row] = i1; g_c2[row] = i2;
        } else {
            g_rlse[row] = mm + logf(ss);
        }
    }
}

// ---------------- K4: exact fp32 re-dot of top-2 + per-token loss ----------------
__global__ __launch_bounds__(128)
void pick_loss_kernel(const float* __restrict__ x,   const float* __restrict__ w,
                      const float* __restrict__ bias,
                      const float* __restrict__ rx,  const float* __restrict__ rw,
                      const float* __restrict__ rbias,
                      const float* __restrict__ adv, const int* __restrict__ amask)
{
    const int row = blockIdx.x;
    const int tid = threadIdx.x;
    const int lane = tid & 31;
    const int wid = tid >> 5;

    const int i1 = g_c1[row];
    const int i2 = g_c2[row];

    const float4* xa = (const float4*)(x + (size_t)row * HDIM);
    const float4* w1 = (const float4*)(w + (size_t)i1 * HDIM);
    const float4* w2 = (const float4*)(w + (size_t)i2 * HDIM);

    float a1 = 0.0f, a2 = 0.0f;
    for (int k = tid; k < HDIM / 4; k += 128) {
        float4 xv = xa[k], v1 = w1[k], v2 = w2[k];
        a1 += xv.x * v1.x + xv.y * v1.y + xv.z * v1.z + xv.w * v1.w;
        a2 += xv.x * v2.x + xv.y * v2.y + xv.z * v2.z + xv.w * v2.w;
    }
#pragma unroll
    for (int off = 16; off >= 1; off >>= 1) {
        a1 += __shfl_down_sync(0xffffffffu, a1, off);
        a2 += __shfl_down_sync(0xffffffffu, a2, off);
    }
    __shared__ float r1[4], r2[4];
    __shared__ int s_chosen;
    __shared__ float s_clogit;
    if (lane == 0) { r1[wid] = a1; r2[wid] = a2; }
    __syncthreads();
    if (tid == 0) {
        float t1 = r1[0] + r1[1] + r1[2] + r1[3] + bias[i1];
        float t2 = r2[0] + r2[1] + r2[2] + r2[3] + bias[i2];
        if (better(t2, i2, t1, i1)) { s_chosen = i2; s_clogit = t2; }
        else                        { s_chosen = i1; s_clogit = t1; }
    }
    __syncthreads();

    const int ch = s_chosen;
    const float4* rxa = (const float4*)(rx + (size_t)row * HDIM);
    const float4* wr  = (const float4*)(rw + (size_t)ch * HDIM);
    float ar = 0.0f;
    for (int k = tid; k < HDIM / 4; k += 128) {
        float4 xv = rxa[k], vv = wr[k];
        ar += xv.x * vv.x + xv.y * vv.y + xv.z * vv.z + xv.w * vv.w;
    }
#pragma unroll
    for (int off = 16; off >= 1; off >>= 1)
        ar += __shfl_down_sync(0xffffffffu, ar, off);
    if (lane == 0) r1[wid] = ar;
    __syncthreads();
    if (tid == 0) {
        float ref_logit = r1[0] + r1[1] + r1[2] + r1[3] + rbias[ch];
        float chosen_lp = s_clogit - g_lse[row];
        float ref_lp = ref_logit - g_rlse[row];
        float advb = adv[row >> 10];
        float ptl = -advb;                     // coef_1 = coef_2 = 1 exactly
        float d = ref_lp - chosen_lp;
        ptl += BETA_C * (expf(d) - d - 1.0f);
        g_tl[row] = ptl * (float)amask[row];
    }
}

// ---------------- K5: final masked mean ----------------
__global__ __launch_bounds__(1024)
void finalize_kernel(const int* __restrict__ amask, float* __restrict__ out, int out_size)
{
    const int tid = threadIdx.x;
    const int lane = tid & 31;
    const int wid = tid >> 5;
    float ls = 0.0f, ms = 0.0f;
    for (int i = tid; i < NROWS; i += 1024) {
        ls += g_tl[i];
        ms += (float)amask[i];
    }
#pragma unroll
    for (int off = 16; off >= 1; off >>= 1) {
        ls += __shfl_down_sync(0xffffffffu, ls, off);
        ms += __shfl_down_sync(0xffffffffu, ms, off);
    }
    __shared__ float sl[32], sm[32];
    __shared__ float s_loss;
    if (lane == 0) { sl[wid] = ls; sm[wid] = ms; }
    __syncthreads();
    if (tid == 0) {
        float tl = 0.0f, tm = 0.0f;
        for (int i = 0; i < 32; i++) { tl += sl[i]; tm += sm[i]; }
        s_loss = tl / fmaxf(tm, 1.0f);
    }
    __syncthreads();
    for (int i = tid; i < out_size; i += 1024) out[i] = s_loss;
}

// ---------------- entry point ----------------
extern "C" void kernel_launch(void* const* d_in, const int* in_sizes, int n_in,
                              void* d_out, int out_size)
{
    const float* x     = (const float*)d_in[0];
    const float* w     = (const float*)d_in[1];
    const float* bias  = (const float*)d_in[2];
    const float* rx    = (const float*)d_in[3];
    const float* rw    = (const float*)d_in[4];
    const float* rb    = (const float*)d_in[5];
    const float* adv   = (const float*)d_in[6];
    const int*   amask = (const int*)d_in[7];

    cudaFuncSetAttribute(gemm_hmma<true>,  cudaFuncAttributeMaxDynamicSharedMemorySize, SMEM_TOTAL);
    cudaFuncSetAttribute(gemm_hmma<false>, cudaFuncAttributeMaxDynamicSharedMemorySize, SMEM_TOTAL);

    __nv_bfloat16 *xb, *wb, *rxb, *rwb;
    cudaGetSymbolAddress((void**)&xb,  g_xb);
    cudaGetSymbolAddress((void**)&wb,  g_wb);
    cudaGetSymbolAddress((void**)&rxb, g_rxb);
    cudaGetSymbolAddress((void**)&rwb, g_rwb);

    {
        int n4x = NROWS * HDIM / 4;
        int n4w = (int)((size_t)VDIM * HDIM / 4);
        cvt_kernel<<<(n4x + 255) / 256, 256>>>(x,  xb,  n4x);
        cvt_kernel<<<(n4w + 255) / 256, 256>>>(w,  wb,  n4w);
        cvt_kernel<<<(n4x + 255) / 256, 256>>>(rx, rxb, n4x);
        cvt_kernel<<<(n4w + 255) / 256, 256>>>(rw, rwb, n4w);
    }

    dim3 grid(MTILES, NCHUNK);   // 32 x 250, m-major for W L2 reuse
    gemm_hmma<true ><<<grid, 256, SMEM_TOTAL>>>(xb,  wb,  bias);
    gemm_hmma<false><<<grid, 256, SMEM_TOTAL>>>(rxb, rwb, rb);

    merge_kernel<true ><<<NROWS / 8, 256>>>();
    merge_kernel<false><<<NROWS / 8, 256>>>();

    pick_loss_kernel<<<NROWS, 128>>>(x, w, bias, rx, rw, rb, adv, amask);
    finalize_kernel<<<1, 1024>>>(amask, (float*)d_out, out_size);
}